// round 4
// baseline (speedup 1.0000x reference)
#include <cuda_runtime.h>
#include <math.h>

#define TK     8
#define NEXP   64
#define CAP    512
#define HDIM   1024
#define IDIM   512
#define ISDIM  2048
#define TMAX   2048

// ---------------- scratch (device globals; no allocation allowed) ----------------
static __device__ int   g_topk_idx[TMAX * TK];
static __device__ float g_topk_w[TMAX * TK];
static __device__ float g_gate_s[TMAX];
static __device__ int   g_counts[NEXP];
static __device__ int   g_tok[NEXP * CAP];
static __device__ float g_wslot[NEXP * CAP];
static __device__ float g_hs[(size_t)TMAX * ISDIM];            // shared SwiGLU activations (16 MB)
static __device__ float g_act[(size_t)NEXP * CAP * IDIM];      // expert SwiGLU activations (64 MB)

__device__ __forceinline__ float siluf(float v) { return v / (1.f + expf(-v)); }

// ---------------- K1: router (logits -> softmax -> top8 -> renorm) + token gate ----------------
__global__ void k_router(const float* __restrict__ x,
                         const float* __restrict__ gw,     // [H, E]
                         const float* __restrict__ sgw)    // [H, 1]
{
    int t   = blockIdx.x;
    int tid = threadIdx.x;
    __shared__ float xs[HDIM];
    __shared__ float logits[NEXP];
    __shared__ float red[256];

    for (int i = tid; i < HDIM; i += 256) xs[i] = x[(size_t)t * HDIM + i];
    __syncthreads();

    if (tid < NEXP) {
        float acc = 0.f;
        #pragma unroll 8
        for (int h = 0; h < HDIM; h++) acc += xs[h] * gw[h * NEXP + tid];
        logits[tid] = acc;
    }
    float p = 0.f;
    for (int i = tid; i < HDIM; i += 256) p += xs[i] * sgw[i];
    red[tid] = p;
    __syncthreads();
    for (int s = 128; s > 0; s >>= 1) {
        if (tid < s) red[tid] += red[tid + s];
        __syncthreads();
    }

    if (tid == 0) {
        g_gate_s[t] = 1.f / (1.f + expf(-red[0]));

        float mx = logits[0];
        #pragma unroll
        for (int e = 1; e < NEXP; e++) mx = fmaxf(mx, logits[e]);
        float pr[NEXP];
        float sum = 0.f;
        #pragma unroll
        for (int e = 0; e < NEXP; e++) { pr[e] = expf(logits[e] - mx); sum += pr[e]; }
        float inv = 1.f / sum;

        int   kidx[TK];
        float kw[TK];
        float wsum = 0.f;
        for (int k = 0; k < TK; k++) {
            int best = 0; float bv = -1.f;
            for (int e = 0; e < NEXP; e++) {
                float v = pr[e];
                if (v > bv) { bv = v; best = e; }   // ties -> lowest index, matches lax.top_k
            }
            pr[best] = -2.f;
            kidx[k] = best;
            kw[k]   = bv * inv;
            wsum   += bv * inv;
        }
        float r = 1.f / wsum;
        for (int k = 0; k < TK; k++) {
            g_topk_idx[t * TK + k] = kidx[k];
            g_topk_w[t * TK + k]   = kw[k] * r;
        }
    }
}

// ---------------- K2: zero counters + atomic slot dispatch ----------------
__global__ void k_zero()
{
    if (threadIdx.x < NEXP) g_counts[threadIdx.x] = 0;
}

__global__ void k_dispatch(int A)
{
    int a = blockIdx.x * 256 + threadIdx.x;
    if (a >= A) return;
    int e    = g_topk_idx[a];
    int slot = atomicAdd(&g_counts[e], 1);
    if (slot < CAP) {
        g_tok[e * CAP + slot]   = a >> 3;       // TK == 8
        g_wslot[e * CAP + slot] = g_topk_w[a];
    }
}

// ---------------- K3/K4: fused gate_up SGEMM + SwiGLU epilogue ----------------
// Tile: 128 rows x 64 act-cols (= 128 GEMM cols). B smem columns interleave
// gate/up in groups of 4 so each thread holds matching (g, u) pairs:
//   smem col c: p=c/8, j=c%8;  j<4 -> gate col n0+p*4+j ; j>=4 -> up col IH+n0+p*4+(j-4)
template<bool EXPERT, int IH>
__global__ void __launch_bounds__(256, 2)
k_gateup(const float* __restrict__ x,     // [T, H] token features
         const float* __restrict__ Bw,    // shared: [H, 2*IH] ; expert: [E, H, 2*IH]
         int Mtot)
{
    const int KD  = HDIM;
    const int ldb = 2 * IH;

    int n0 = blockIdx.x * 64;
    int m0 = blockIdx.y * 128;
    int e = 0, Mcnt = Mtot;
    const int* tokp = 0;
    if (EXPERT) {
        e = blockIdx.z;
        int c = g_counts[e];
        Mcnt = (c < CAP) ? c : CAP;
        if (m0 >= Mcnt) return;
        Bw  += (size_t)e * KD * ldb;
        tokp = &g_tok[e * CAP];
    }
    float* out = EXPERT ? g_act : g_hs;

    __shared__ float As[8][128];
    __shared__ float Bs[8][128];

    int tid = threadIdx.x;
    int tx = tid & 15, ty = tid >> 4;

    // A load: 128 rows x 8 k, one float4/thread
    int arow = tid >> 1;
    int aoff = (tid & 1) * 4;
    bool avalid = (m0 + arow) < Mcnt;
    const float* aptr = 0;
    if (avalid) {
        int row = m0 + arow;
        int src = EXPERT ? tokp[row] : row;
        aptr = x + (size_t)src * KD + aoff;
    }

    // B load: 8 k-rows x 128 cols, one float4/thread, gate/up interleaved
    int brow = tid >> 5;
    int c4   = (tid & 31) * 4;
    int half = (c4 >> 2) & 1;
    int gcol = n0 + (c4 >> 3) * 4 + half * IH;
    const float* bptr = Bw + (size_t)brow * ldb + gcol;

    float acc[8][8] = {};
    for (int k0 = 0; k0 < KD; k0 += 8) {
        float4 av = avalid ? *(const float4*)(aptr + k0) : make_float4(0.f, 0.f, 0.f, 0.f);
        float4 bv = *(const float4*)(bptr + (size_t)k0 * ldb);
        As[aoff + 0][arow] = av.x;
        As[aoff + 1][arow] = av.y;
        As[aoff + 2][arow] = av.z;
        As[aoff + 3][arow] = av.w;
        *(float4*)&Bs[brow][c4] = bv;
        __syncthreads();
        #pragma unroll
        for (int kk = 0; kk < 8; kk++) {
            float4 a0 = *(const float4*)&As[kk][ty * 8];
            float4 a1 = *(const float4*)&As[kk][ty * 8 + 4];
            float4 b0 = *(const float4*)&Bs[kk][tx * 8];
            float4 b1 = *(const float4*)&Bs[kk][tx * 8 + 4];
            float ar[8] = {a0.x, a0.y, a0.z, a0.w, a1.x, a1.y, a1.z, a1.w};
            float br[8] = {b0.x, b0.y, b0.z, b0.w, b1.x, b1.y, b1.z, b1.w};
            #pragma unroll
            for (int i = 0; i < 8; i++)
                #pragma unroll
                for (int j = 0; j < 8; j++)
                    acc[i][j] += ar[i] * br[j];
        }
        __syncthreads();
    }

    // epilogue: act = silu(g) * u
    #pragma unroll
    for (int i = 0; i < 8; i++) {
        int row = m0 + ty * 8 + i;
        if (row >= Mcnt) continue;
        float4 o;
        o.x = siluf(acc[i][0]) * acc[i][4];
        o.y = siluf(acc[i][1]) * acc[i][5];
        o.z = siluf(acc[i][2]) * acc[i][6];
        o.w = siluf(acc[i][3]) * acc[i][7];
        size_t orow = EXPERT ? ((size_t)e * CAP + row) : (size_t)row;
        *(float4*)(out + orow * IH + n0 + tx * 4) = o;
    }
}

// ---------------- K5/K6: down SGEMM ----------------
// shared:  y[t,h]  = (hs @ Wd) * gate_s[t]          (writes every output element)
// expert:  y[tok,h] += w * (act @ Wd)               (atomicAdd combine)
template<bool EXPERT, int KD>
__global__ void __launch_bounds__(256, 2)
k_down(const float* __restrict__ Bw,     // shared: [Is, H] ; expert: [E, I, H]
       float* __restrict__ y,
       int Mtot)
{
    int n0 = blockIdx.x * 128;
    int m0 = blockIdx.y * 128;
    int e = 0, Mcnt = Mtot;
    const float* Ain = EXPERT ? g_act : g_hs;
    if (EXPERT) {
        e = blockIdx.z;
        int c = g_counts[e];
        Mcnt = (c < CAP) ? c : CAP;
        if (m0 >= Mcnt) return;
        Ain += (size_t)e * CAP * IDIM;
        Bw  += (size_t)e * IDIM * HDIM;
    }

    __shared__ float As[8][128];
    __shared__ float Bs[8][128];

    int tid = threadIdx.x;
    int tx = tid & 15, ty = tid >> 4;

    int arow = tid >> 1;
    int aoff = (tid & 1) * 4;
    bool avalid = (m0 + arow) < Mcnt;
    const float* aptr = avalid ? (Ain + (size_t)(m0 + arow) * KD + aoff) : 0;

    int brow  = tid >> 5;
    int bcol4 = (tid & 31) * 4;
    const float* bptr = Bw + (size_t)brow * HDIM + n0 + bcol4;

    float acc[8][8] = {};
    for (int k0 = 0; k0 < KD; k0 += 8) {
        float4 av = avalid ? *(const float4*)(aptr + k0) : make_float4(0.f, 0.f, 0.f, 0.f);
        float4 bv = *(const float4*)(bptr + (size_t)k0 * HDIM);
        As[aoff + 0][arow] = av.x;
        As[aoff + 1][arow] = av.y;
        As[aoff + 2][arow] = av.z;
        As[aoff + 3][arow] = av.w;
        *(float4*)&Bs[brow][bcol4] = bv;
        __syncthreads();
        #pragma unroll
        for (int kk = 0; kk < 8; kk++) {
            float4 a0 = *(const float4*)&As[kk][ty * 8];
            float4 a1 = *(const float4*)&As[kk][ty * 8 + 4];
            float4 b0 = *(const float4*)&Bs[kk][tx * 8];
            float4 b1 = *(const float4*)&Bs[kk][tx * 8 + 4];
            float ar[8] = {a0.x, a0.y, a0.z, a0.w, a1.x, a1.y, a1.z, a1.w};
            float br[8] = {b0.x, b0.y, b0.z, b0.w, b1.x, b1.y, b1.z, b1.w};
            #pragma unroll
            for (int i = 0; i < 8; i++)
                #pragma unroll
                for (int j = 0; j < 8; j++)
                    acc[i][j] += ar[i] * br[j];
        }
        __syncthreads();
    }

    #pragma unroll
    for (int i = 0; i < 8; i++) {
        int row = m0 + ty * 8 + i;
        if (row >= Mcnt) continue;
        if (EXPERT) {
            int   tok = g_tok[e * CAP + row];
            float w   = g_wslot[e * CAP + row];
            float* yr = y + (size_t)tok * HDIM + n0 + tx * 8;
            #pragma unroll
            for (int j = 0; j < 8; j++) atomicAdd(yr + j, w * acc[i][j]);
        } else {
            float gs = g_gate_s[row];
            float4 o0, o1;
            o0.x = acc[i][0] * gs; o0.y = acc[i][1] * gs; o0.z = acc[i][2] * gs; o0.w = acc[i][3] * gs;
            o1.x = acc[i][4] * gs; o1.y = acc[i][5] * gs; o1.z = acc[i][6] * gs; o1.w = acc[i][7] * gs;
            float* yr = y + (size_t)row * HDIM + n0 + tx * 8;
            *(float4*)(yr)     = o0;
            *(float4*)(yr + 4) = o1;
        }
    }
}

// ---------------- launch ----------------
extern "C" void kernel_launch(void* const* d_in, const int* in_sizes, int n_in,
                              void* d_out, int out_size)
{
    const float* x    = (const float*)d_in[0];   // hidden_states [B,S,H]
    const float* gw   = (const float*)d_in[1];   // gate_w [H,E]
    const float* sgw  = (const float*)d_in[2];   // shared_gate_w [H,1]
    const float* sguw = (const float*)d_in[3];   // shared_gate_up_w [H,2*Is]
    const float* sdw  = (const float*)d_in[4];   // shared_down_w [Is,H]
    const float* egu  = (const float*)d_in[5];   // expert_gate_up_w [E,H,2*I]
    const float* edw  = (const float*)d_in[6];   // expert_down_w [E,I,H]
    float* y = (float*)d_out;

    int T = in_sizes[0] / HDIM;   // 2048

    // router + token gate
    k_router<<<T, 256>>>(x, gw, sgw);

    // dispatch
    k_zero<<<1, 64>>>();
    k_dispatch<<<(T * TK + 255) / 256, 256>>>(T * TK);

    // shared expert gate_up (writes g_hs)
    {
        dim3 g(ISDIM / 64, T / 128);
        k_gateup<false, ISDIM><<<g, 256>>>(x, sguw, T);
    }
    // expert gate_up (writes g_act), row-tiles beyond count early-exit
    {
        dim3 g(IDIM / 64, CAP / 128, NEXP);
        k_gateup<true, IDIM><<<g, 256>>>(x, egu, CAP);
    }
    // shared down: initializes every element of y with gated shared output
    {
        dim3 g(HDIM / 128, T / 128);
        k_down<false, ISDIM><<<g, 256>>>(sdw, y, T);
    }
    // expert down: atomic combine into y
    {
        dim3 g(HDIM / 128, CAP / 128, NEXP);
        k_down<true, IDIM><<<g, 256>>>(edw, y, CAP);
    }
}

// round 5
// speedup vs baseline: 1.0012x; 1.0012x over previous
#include <cuda_runtime.h>
#include <math.h>

#define TK     8
#define NEXP   64
#define CAP    512
#define HDIM   1024
#define IDIM   512
#define ISDIM  2048
#define TMAX   2048

// ---------------- scratch (device globals; no allocation allowed) ----------------
static __device__ int   g_topk_idx[TMAX * TK];
static __device__ float g_topk_w[TMAX * TK];
static __device__ float g_gate_s[TMAX];
static __device__ int   g_counts[NEXP];
static __device__ int   g_tok[NEXP * CAP];
static __device__ float g_wslot[NEXP * CAP];
static __device__ float g_hs[(size_t)TMAX * ISDIM];            // shared SwiGLU activations (16 MB)
static __device__ float g_act[(size_t)NEXP * CAP * IDIM];      // expert SwiGLU activations (64 MB)

__device__ __forceinline__ float siluf(float v) { return v / (1.f + expf(-v)); }

// ---------------- K1: router (logits -> softmax -> top8 -> renorm) + token gate ----------------
__global__ void k_router(const float* __restrict__ x,
                         const float* __restrict__ gw,     // [H, E]
                         const float* __restrict__ sgw)    // [H, 1]
{
    int t   = blockIdx.x;
    int tid = threadIdx.x;
    __shared__ float xs[HDIM];
    __shared__ float logits[NEXP];
    __shared__ float red[256];

    for (int i = tid; i < HDIM; i += 256) xs[i] = x[(size_t)t * HDIM + i];
    __syncthreads();

    if (tid < NEXP) {
        float acc = 0.f;
        #pragma unroll 8
        for (int h = 0; h < HDIM; h++) acc += xs[h] * gw[h * NEXP + tid];
        logits[tid] = acc;
    }
    float p = 0.f;
    for (int i = tid; i < HDIM; i += 256) p += xs[i] * sgw[i];
    red[tid] = p;
    __syncthreads();
    for (int s = 128; s > 0; s >>= 1) {
        if (tid < s) red[tid] += red[tid + s];
        __syncthreads();
    }

    if (tid == 0) {
        g_gate_s[t] = 1.f / (1.f + expf(-red[0]));

        float mx = logits[0];
        #pragma unroll
        for (int e = 1; e < NEXP; e++) mx = fmaxf(mx, logits[e]);
        float pr[NEXP];
        float sum = 0.f;
        #pragma unroll
        for (int e = 0; e < NEXP; e++) { pr[e] = expf(logits[e] - mx); sum += pr[e]; }
        float inv = 1.f / sum;

        int   kidx[TK];
        float kw[TK];
        float wsum = 0.f;
        for (int k = 0; k < TK; k++) {
            int best = 0; float bv = -1.f;
            for (int e = 0; e < NEXP; e++) {
                float v = pr[e];
                if (v > bv) { bv = v; best = e; }   // ties -> lowest index, matches lax.top_k
            }
            pr[best] = -2.f;
            kidx[k] = best;
            kw[k]   = bv * inv;
            wsum   += bv * inv;
        }
        float r = 1.f / wsum;
        for (int k = 0; k < TK; k++) {
            g_topk_idx[t * TK + k] = kidx[k];
            g_topk_w[t * TK + k]   = kw[k] * r;
        }
    }
}

// ---------------- K2: zero counters + atomic slot dispatch ----------------
__global__ void k_zero()
{
    if (threadIdx.x < NEXP) g_counts[threadIdx.x] = 0;
}

__global__ void k_dispatch(int A)
{
    int a = blockIdx.x * 256 + threadIdx.x;
    if (a >= A) return;
    int e    = g_topk_idx[a];
    int slot = atomicAdd(&g_counts[e], 1);
    if (slot < CAP) {
        g_tok[e * CAP + slot]   = a >> 3;       // TK == 8
        g_wslot[e * CAP + slot] = g_topk_w[a];
    }
}

// ---------------- K3/K4: fused gate_up SGEMM + SwiGLU epilogue ----------------
// Tile: 128 rows x 64 act-cols (= 128 GEMM cols). B smem columns interleave
// gate/up in groups of 4 so each thread holds matching (g, u) pairs:
//   smem col c: p=c/8, j=c%8;  j<4 -> gate col n0+p*4+j ; j>=4 -> up col IH+n0+p*4+(j-4)
template<bool EXPERT, int IH>
__global__ void __launch_bounds__(256, 2)
k_gateup(const float* __restrict__ x,     // [T, H] token features
         const float* __restrict__ Bw,    // shared: [H, 2*IH] ; expert: [E, H, 2*IH]
         int Mtot)
{
    const int KD  = HDIM;
    const int ldb = 2 * IH;

    int n0 = blockIdx.x * 64;
    int m0 = blockIdx.y * 128;
    int e = 0, Mcnt = Mtot;
    const int* tokp = 0;
    if (EXPERT) {
        e = blockIdx.z;
        int c = g_counts[e];
        Mcnt = (c < CAP) ? c : CAP;
        if (m0 >= Mcnt) return;
        Bw  += (size_t)e * KD * ldb;
        tokp = &g_tok[e * CAP];
    }
    float* out = EXPERT ? g_act : g_hs;

    __shared__ float As[8][128];
    __shared__ float Bs[8][128];

    int tid = threadIdx.x;
    int tx = tid & 15, ty = tid >> 4;

    // A load: 128 rows x 8 k, one float4/thread
    int arow = tid >> 1;
    int aoff = (tid & 1) * 4;
    bool avalid = (m0 + arow) < Mcnt;
    const float* aptr = 0;
    if (avalid) {
        int row = m0 + arow;
        int src = EXPERT ? tokp[row] : row;
        aptr = x + (size_t)src * KD + aoff;
    }

    // B load: 8 k-rows x 128 cols, one float4/thread, gate/up interleaved
    int brow = tid >> 5;
    int c4   = (tid & 31) * 4;
    int half = (c4 >> 2) & 1;
    int gcol = n0 + (c4 >> 3) * 4 + half * IH;
    const float* bptr = Bw + (size_t)brow * ldb + gcol;

    float acc[8][8] = {};
    for (int k0 = 0; k0 < KD; k0 += 8) {
        float4 av = avalid ? *(const float4*)(aptr + k0) : make_float4(0.f, 0.f, 0.f, 0.f);
        float4 bv = *(const float4*)(bptr + (size_t)k0 * ldb);
        As[aoff + 0][arow] = av.x;
        As[aoff + 1][arow] = av.y;
        As[aoff + 2][arow] = av.z;
        As[aoff + 3][arow] = av.w;
        *(float4*)&Bs[brow][c4] = bv;
        __syncthreads();
        #pragma unroll
        for (int kk = 0; kk < 8; kk++) {
            float4 a0 = *(const float4*)&As[kk][ty * 8];
            float4 a1 = *(const float4*)&As[kk][ty * 8 + 4];
            float4 b0 = *(const float4*)&Bs[kk][tx * 8];
            float4 b1 = *(const float4*)&Bs[kk][tx * 8 + 4];
            float ar[8] = {a0.x, a0.y, a0.z, a0.w, a1.x, a1.y, a1.z, a1.w};
            float br[8] = {b0.x, b0.y, b0.z, b0.w, b1.x, b1.y, b1.z, b1.w};
            #pragma unroll
            for (int i = 0; i < 8; i++)
                #pragma unroll
                for (int j = 0; j < 8; j++)
                    acc[i][j] += ar[i] * br[j];
        }
        __syncthreads();
    }

    // epilogue: act = silu(g) * u
    #pragma unroll
    for (int i = 0; i < 8; i++) {
        int row = m0 + ty * 8 + i;
        if (row >= Mcnt) continue;
        float4 o;
        o.x = siluf(acc[i][0]) * acc[i][4];
        o.y = siluf(acc[i][1]) * acc[i][5];
        o.z = siluf(acc[i][2]) * acc[i][6];
        o.w = siluf(acc[i][3]) * acc[i][7];
        size_t orow = EXPERT ? ((size_t)e * CAP + row) : (size_t)row;
        *(float4*)(out + orow * IH + n0 + tx * 4) = o;
    }
}

// ---------------- K5/K6: down SGEMM ----------------
// shared:  y[t,h]  = (hs @ Wd) * gate_s[t]          (writes every output element)
// expert:  y[tok,h] += w * (act @ Wd)               (atomicAdd combine)
template<bool EXPERT, int KD>
__global__ void __launch_bounds__(256, 2)
k_down(const float* __restrict__ Bw,     // shared: [Is, H] ; expert: [E, I, H]
       float* __restrict__ y,
       int Mtot)
{
    int n0 = blockIdx.x * 128;
    int m0 = blockIdx.y * 128;
    int e = 0, Mcnt = Mtot;
    const float* Ain = EXPERT ? g_act : g_hs;
    if (EXPERT) {
        e = blockIdx.z;
        int c = g_counts[e];
        Mcnt = (c < CAP) ? c : CAP;
        if (m0 >= Mcnt) return;
        Ain += (size_t)e * CAP * IDIM;
        Bw  += (size_t)e * IDIM * HDIM;
    }

    __shared__ float As[8][128];
    __shared__ float Bs[8][128];

    int tid = threadIdx.x;
    int tx = tid & 15, ty = tid >> 4;

    int arow = tid >> 1;
    int aoff = (tid & 1) * 4;
    bool avalid = (m0 + arow) < Mcnt;
    const float* aptr = avalid ? (Ain + (size_t)(m0 + arow) * KD + aoff) : 0;

    int brow  = tid >> 5;
    int bcol4 = (tid & 31) * 4;
    const float* bptr = Bw + (size_t)brow * HDIM + n0 + bcol4;

    float acc[8][8] = {};
    for (int k0 = 0; k0 < KD; k0 += 8) {
        float4 av = avalid ? *(const float4*)(aptr + k0) : make_float4(0.f, 0.f, 0.f, 0.f);
        float4 bv = *(const float4*)(bptr + (size_t)k0 * HDIM);
        As[aoff + 0][arow] = av.x;
        As[aoff + 1][arow] = av.y;
        As[aoff + 2][arow] = av.z;
        As[aoff + 3][arow] = av.w;
        *(float4*)&Bs[brow][bcol4] = bv;
        __syncthreads();
        #pragma unroll
        for (int kk = 0; kk < 8; kk++) {
            float4 a0 = *(const float4*)&As[kk][ty * 8];
            float4 a1 = *(const float4*)&As[kk][ty * 8 + 4];
            float4 b0 = *(const float4*)&Bs[kk][tx * 8];
            float4 b1 = *(const float4*)&Bs[kk][tx * 8 + 4];
            float ar[8] = {a0.x, a0.y, a0.z, a0.w, a1.x, a1.y, a1.z, a1.w};
            float br[8] = {b0.x, b0.y, b0.z, b0.w, b1.x, b1.y, b1.z, b1.w};
            #pragma unroll
            for (int i = 0; i < 8; i++)
                #pragma unroll
                for (int j = 0; j < 8; j++)
                    acc[i][j] += ar[i] * br[j];
        }
        __syncthreads();
    }

    #pragma unroll
    for (int i = 0; i < 8; i++) {
        int row = m0 + ty * 8 + i;
        if (row >= Mcnt) continue;
        if (EXPERT) {
            int   tok = g_tok[e * CAP + row];
            float w   = g_wslot[e * CAP + row];
            float* yr = y + (size_t)tok * HDIM + n0 + tx * 8;
            #pragma unroll
            for (int j = 0; j < 8; j++) atomicAdd(yr + j, w * acc[i][j]);
        } else {
            float gs = g_gate_s[row];
            float4 o0, o1;
            o0.x = acc[i][0] * gs; o0.y = acc[i][1] * gs; o0.z = acc[i][2] * gs; o0.w = acc[i][3] * gs;
            o1.x = acc[i][4] * gs; o1.y = acc[i][5] * gs; o1.z = acc[i][6] * gs; o1.w = acc[i][7] * gs;
            float* yr = y + (size_t)row * HDIM + n0 + tx * 8;
            *(float4*)(yr)     = o0;
            *(float4*)(yr + 4) = o1;
        }
    }
}

// ---------------- launch ----------------
extern "C" void kernel_launch(void* const* d_in, const int* in_sizes, int n_in,
                              void* d_out, int out_size)
{
    const float* x    = (const float*)d_in[0];   // hidden_states [B,S,H]
    const float* gw   = (const float*)d_in[1];   // gate_w [H,E]
    const float* sgw  = (const float*)d_in[2];   // shared_gate_w [H,1]
    const float* sguw = (const float*)d_in[3];   // shared_gate_up_w [H,2*Is]
    const float* sdw  = (const float*)d_in[4];   // shared_down_w [Is,H]
    const float* egu  = (const float*)d_in[5];   // expert_gate_up_w [E,H,2*I]
    const float* edw  = (const float*)d_in[6];   // expert_down_w [E,I,H]
    float* y = (float*)d_out;

    int T = in_sizes[0] / HDIM;   // 2048

    // router + token gate
    k_router<<<T, 256>>>(x, gw, sgw);

    // dispatch
    k_zero<<<1, 64>>>();
    k_dispatch<<<(T * TK + 255) / 256, 256>>>(T * TK);

    // shared expert gate_up (writes g_hs)
    {
        dim3 g(ISDIM / 64, T / 128);
        k_gateup<false, ISDIM><<<g, 256>>>(x, sguw, T);
    }
    // expert gate_up (writes g_act), row-tiles beyond count early-exit
    {
        dim3 g(IDIM / 64, CAP / 128, NEXP);
        k_gateup<true, IDIM><<<g, 256>>>(x, egu, CAP);
    }
    // shared down: initializes every element of y with gated shared output
    {
        dim3 g(HDIM / 128, T / 128);
        k_down<false, ISDIM><<<g, 256>>>(sdw, y, T);
    }
    // expert down: atomic combine into y
    {
        dim3 g(HDIM / 128, CAP / 128, NEXP);
        k_down<true, IDIM><<<g, 256>>>(edw, y, CAP);
    }
}